// round 3
// baseline (speedup 1.0000x reference)
#include <cuda_runtime.h>
#include <math.h>

#define V_   10475
#define J_   55
#define B_   512
#define V3_  (V_*3)     // 31425
#define K486 486

#define TV 16   // vertices per block (main kernel)
#define TB 64   // batches per block
#define KT 32   // K-chunk

// -------- device scratch (no allocations allowed) --------
__device__ __align__(16) float g_vbase[V_*3];
__device__ float g_yoff;
__device__ float g_Jbase[J_*3];
__device__ float g_JE[J_*3*10];
__device__ __align__(16) float g_pf_t[K486*B_];     // transposed pose_feature: [k][b]
__device__ __align__(16) float g_A[B_*J_*12];       // per-joint 3x4 skinning matrices

// ============== Kernel 1: vbase = v_template + shapedirs @ shape ==============
__global__ void k_vbase(const float* __restrict__ vt,
                        const float* __restrict__ shapedirs,
                        const float* __restrict__ shape)
{
    int i = blockIdx.x*256 + threadIdx.x;
    if (i < V3_) {
        float acc = vt[i];
        #pragma unroll
        for (int s = 0; s < 10; s++) acc += shape[s] * shapedirs[i*10 + s];
        g_vbase[i] = acc;
    }
}

// ============== Kernel 2: y offset = -min(v_template[:,1]) ==============
__global__ void k_ymin(const float* __restrict__ vt)
{
    __shared__ float red[1024];
    float m = 1e30f;
    for (int v = threadIdx.x; v < V_; v += 1024) m = fminf(m, vt[v*3 + 1]);
    red[threadIdx.x] = m;
    __syncthreads();
    for (int s = 512; s > 0; s >>= 1) {
        if (threadIdx.x < s) red[threadIdx.x] = fminf(red[threadIdx.x], red[threadIdx.x + s]);
        __syncthreads();
    }
    if (threadIdx.x == 0) g_yoff = -red[0];
}

// ============== Kernel 3: Jbase(j,c) and JE(j,c,e) = JR @ [vbase | exprdirs] ==============
__global__ void k_jreg(const float* __restrict__ JR,
                       const float* __restrict__ exprdirs)
{
    int j = blockIdx.x;
    int tid = threadIdx.x;            // 128 threads
    float acc[33];
    #pragma unroll
    for (int i = 0; i < 33; i++) acc[i] = 0.f;

    for (int v = tid; v < V_; v += 128) {
        float jr = JR[j*V_ + v];
        acc[0] += jr * g_vbase[v*3 + 0];
        acc[1] += jr * g_vbase[v*3 + 1];
        acc[2] += jr * g_vbase[v*3 + 2];
        const float* ed = &exprdirs[v*30];
        #pragma unroll
        for (int i = 0; i < 30; i++) acc[3+i] += jr * ed[i];
    }
    // warp reduce then cross-warp
    __shared__ float red[4][33];
    int lane = tid & 31, w = tid >> 5;
    #pragma unroll
    for (int i = 0; i < 33; i++) {
        float v = acc[i];
        for (int off = 16; off > 0; off >>= 1) v += __shfl_down_sync(0xffffffffu, v, off);
        if (lane == 0) red[w][i] = v;
    }
    __syncthreads();
    if (tid < 33) {
        float s = red[0][tid] + red[1][tid] + red[2][tid] + red[3][tid];
        if (tid < 3) g_Jbase[j*3 + tid] = s;
        else         g_JE[j*30 + (tid-3)] = s;
    }
}

// ============== Kernel 4: per-batch rodrigues, pose_feature, joints, chain, A ==============
__global__ void k_pose(const float* __restrict__ body,
                       const float* __restrict__ hand,
                       const float* __restrict__ head,
                       const float* __restrict__ pelvis,
                       const float* __restrict__ hand_mean,
                       const float* __restrict__ expression)
{
    int b = blockIdx.x;
    int tid = threadIdx.x;            // 64 threads
    __shared__ float R_s[J_][9];
    __shared__ float jnt[J_][3];

    if (tid < J_) {
        float r0, r1, r2;
        if (tid == 0) {
            r0 = pelvis[b*3+0]; r1 = pelvis[b*3+1]; r2 = pelvis[b*3+2];
        } else if (tid <= 21) {
            int i = tid - 1;
            r0 = body[(b*21+i)*3+0]; r1 = body[(b*21+i)*3+1]; r2 = body[(b*21+i)*3+2];
        } else if (tid <= 24) {
            int i = tid - 22;
            r0 = head[(b*3+i)*3+0]; r1 = head[(b*3+i)*3+1]; r2 = head[(b*3+i)*3+2];
        } else {
            int h = tid - 25;
            r0 = hand[(b*30+h)*3+0] + hand_mean[h*3+0];
            r1 = hand[(b*30+h)*3+1] + hand_mean[h*3+1];
            r2 = hand[(b*30+h)*3+2] + hand_mean[h*3+2];
        }
        float a2  = r0*r0 + r1*r1 + r2*r2 + 1e-12f;
        float ang = sqrtf(a2);
        float inv = 1.0f / ang;
        float kx = r0*inv, ky = r1*inv, kz = r2*inv;
        float s, c;
        __sincosf(ang, &s, &c);
        // use precise versions: tolerance is generous but keep it clean
        s = sinf(ang); c = cosf(ang);
        float t1 = 1.0f - c;
        float R[9];
        R[0] = c + t1*kx*kx;     R[1] = t1*kx*ky - s*kz;  R[2] = t1*kx*kz + s*ky;
        R[3] = t1*kx*ky + s*kz;  R[4] = c + t1*ky*ky;     R[5] = t1*ky*kz - s*kx;
        R[6] = t1*kx*kz - s*ky;  R[7] = t1*ky*kz + s*kx;  R[8] = c + t1*kz*kz;
        #pragma unroll
        for (int i = 0; i < 9; i++) R_s[tid][i] = R[i];
        if (tid >= 1) {
            #pragma unroll
            for (int i = 0; i < 9; i++) {
                float d = (i == 0 || i == 4 || i == 8) ? 1.0f : 0.0f;
                g_pf_t[((tid-1)*9 + i)*B_ + b] = R[i] - d;
            }
        }
        // joints(b, tid, c) = Jbase + JE . expr
        #pragma unroll
        for (int cc = 0; cc < 3; cc++) {
            float acc = g_Jbase[tid*3 + cc];
            #pragma unroll
            for (int e = 0; e < 10; e++)
                acc += expression[b*10 + e] * g_JE[(tid*3 + cc)*10 + e];
            jnt[tid][cc] = acc;
        }
    }
    __syncthreads();

    if (tid < 3) {
        int r = tid;
        // G_0 row r
        float g0 = R_s[0][r*3+0], g1 = R_s[0][r*3+1], g2 = R_s[0][r*3+2], g3 = jnt[0][r];
        // A_0
        g_A[(b*J_ + 0)*12 + r*4 + 0] = g0;
        g_A[(b*J_ + 0)*12 + r*4 + 1] = g1;
        g_A[(b*J_ + 0)*12 + r*4 + 2] = g2;
        g_A[(b*J_ + 0)*12 + r*4 + 3] = g3 - (g0*jnt[0][0] + g1*jnt[0][1] + g2*jnt[0][2]);
        for (int j = 1; j < J_; j++) {
            float t0 = jnt[j][0] - jnt[j-1][0];
            float t1 = jnt[j][1] - jnt[j-1][1];
            float t2 = jnt[j][2] - jnt[j-1][2];
            float n0 = g0*R_s[j][0] + g1*R_s[j][3] + g2*R_s[j][6];
            float n1 = g0*R_s[j][1] + g1*R_s[j][4] + g2*R_s[j][7];
            float n2 = g0*R_s[j][2] + g1*R_s[j][5] + g2*R_s[j][8];
            float n3 = g0*t0 + g1*t1 + g2*t2 + g3;
            g0 = n0; g1 = n1; g2 = n2; g3 = n3;
            g_A[(b*J_ + j)*12 + r*4 + 0] = g0;
            g_A[(b*J_ + j)*12 + r*4 + 1] = g1;
            g_A[(b*J_ + j)*12 + r*4 + 2] = g2;
            g_A[(b*J_ + j)*12 + r*4 + 3] = g3 - (g0*jnt[j][0] + g1*jnt[j][1] + g2*jnt[j][2]);
        }
    }
}

// ============== Kernel 5: fused pose-blendshape GEMM + expression + LBS + epilogue ==============
__global__ void __launch_bounds__(256) k_main(const float* __restrict__ posedirs,
                                              const float* __restrict__ lbsw,
                                              const float* __restrict__ exprdirs,
                                              const float* __restrict__ expression,
                                              const float* __restrict__ gtrans,
                                              float* __restrict__ out)
{
    __shared__ float pf_s[KT][TB];                  // 8 KB
    __shared__ float pd_s[KT][TV*3];                // 6 KB
    __shared__ float ed_s[TV][30];                  // 1.9 KB
    __shared__ float ex_s[TB][10];                  // 2.5 KB
    __shared__ __align__(16) float A_s[8][TB][12];  // 24 KB
    __shared__ float W_s[TV][56];                   // 3.5 KB
    __shared__ float vb_s[TV][3];

    const int v0 = blockIdx.x * TV;
    const int b0 = blockIdx.y * TB;
    const int tid = threadIdx.x;
    const int vx = tid & 15;        // vertex within tile
    const int by = tid >> 4;        // batch sub-index (thread handles by, by+16, by+32, by+48)

    // ---- one-time tile loads ----
    for (int i = tid; i < TV*56; i += 256) {
        int vv = i / 56, j = i % 56;
        float w = 0.f;
        if (j < J_ && v0 + vv < V_) w = lbsw[(v0+vv)*J_ + j];
        W_s[vv][j] = w;
    }
    for (int i = tid; i < TV*30; i += 256) {
        int vv = i / 30, e = i % 30;
        ed_s[vv][e] = (v0 + vv < V_) ? exprdirs[(v0+vv)*30 + e] : 0.f;
    }
    for (int i = tid; i < TB*10; i += 256)
        ex_s[i/10][i%10] = expression[(b0 + i/10)*10 + (i%10)];
    for (int i = tid; i < TV*3; i += 256)
        vb_s[i/3][i%3] = (v0 + i/3 < V_) ? g_vbase[(v0 + i/3)*3 + (i%3)] : 0.f;

    // ---- phase A: delta(b, v, c) = PF(b,:) @ posedirs(:, 3v+c) ----
    float d[4][3];
    #pragma unroll
    for (int bi = 0; bi < 4; bi++) { d[bi][0] = d[bi][1] = d[bi][2] = 0.f; }

    for (int k0 = 0; k0 < K486; k0 += KT) {
        __syncthreads();
        for (int i = tid; i < KT*TB; i += 256) {
            int k = i / TB, bb = i % TB;
            pf_s[k][bb] = (k0 + k < K486) ? g_pf_t[(k0+k)*B_ + b0 + bb] : 0.f;
        }
        for (int i = tid; i < KT*TV*3; i += 256) {
            int k = i / (TV*3), c = i % (TV*3);
            int col = v0*3 + c;
            pd_s[k][c] = (k0 + k < K486 && col < V3_) ? posedirs[(size_t)(k0+k)*V3_ + col] : 0.f;
        }
        __syncthreads();
        #pragma unroll 8
        for (int k = 0; k < KT; k++) {
            float p0 = pd_s[k][vx*3+0];
            float p1 = pd_s[k][vx*3+1];
            float p2 = pd_s[k][vx*3+2];
            #pragma unroll
            for (int bi = 0; bi < 4; bi++) {
                float f = pf_s[k][by + bi*16];
                d[bi][0] += f*p0; d[bi][1] += f*p1; d[bi][2] += f*p2;
            }
        }
    }

    // ---- phase B: v_posed = vbase + delta + exprdirs . expression ----
    float px[4], py[4], pz[4];
    #pragma unroll
    for (int bi = 0; bi < 4; bi++) {
        int bb = by + bi*16;
        float x = vb_s[vx][0] + d[bi][0];
        float y = vb_s[vx][1] + d[bi][1];
        float z = vb_s[vx][2] + d[bi][2];
        #pragma unroll
        for (int e = 0; e < 10; e++) {
            float ex = ex_s[bb][e];
            x += ex * ed_s[vx][e];
            y += ex * ed_s[vx][10+e];
            z += ex * ed_s[vx][20+e];
        }
        px[bi] = x; py[bi] = y; pz[bi] = z;
    }

    // ---- phase C: LBS — T(b,v) = sum_j w(v,j) A(b,j) ----
    float t[4][12];
    #pragma unroll
    for (int bi = 0; bi < 4; bi++)
        #pragma unroll
        for (int q = 0; q < 12; q++) t[bi][q] = 0.f;

    for (int j0 = 0; j0 < J_; j0 += 8) {
        __syncthreads();
        for (int i = tid; i < TB*8*3; i += 256) {
            int bb  = i / 24;
            int rem = i % 24;
            int jj  = rem / 3;
            int q   = rem % 3;
            float4 val = make_float4(0.f, 0.f, 0.f, 0.f);
            if (j0 + jj < J_)
                val = *reinterpret_cast<const float4*>(&g_A[((size_t)(b0+bb)*J_ + (j0+jj))*12 + q*4]);
            *reinterpret_cast<float4*>(&A_s[jj][bb][q*4]) = val;
        }
        __syncthreads();
        #pragma unroll
        for (int jj = 0; jj < 8; jj++) {
            float w = W_s[vx][j0 + jj];
            #pragma unroll
            for (int bi = 0; bi < 4; bi++) {
                const float4* ap = reinterpret_cast<const float4*>(&A_s[jj][by + bi*16][0]);
                float4 a0 = ap[0], a1 = ap[1], a2 = ap[2];
                t[bi][0]  += w*a0.x; t[bi][1]  += w*a0.y; t[bi][2]  += w*a0.z; t[bi][3]  += w*a0.w;
                t[bi][4]  += w*a1.x; t[bi][5]  += w*a1.y; t[bi][6]  += w*a1.z; t[bi][7]  += w*a1.w;
                t[bi][8]  += w*a2.x; t[bi][9]  += w*a2.y; t[bi][10] += w*a2.z; t[bi][11] += w*a2.w;
            }
        }
    }

    // ---- epilogue ----
    int v = v0 + vx;
    if (v < V_) {
        float yoff = g_yoff;
        #pragma unroll
        for (int bi = 0; bi < 4; bi++) {
            int b = b0 + by + bi*16;
            float gx = gtrans[b*3+0], gy = gtrans[b*3+1], gz = gtrans[b*3+2];
            float x = px[bi], y = py[bi], z = pz[bi];
            float ox = t[bi][0]*x + t[bi][1]*y + t[bi][2] *z + t[bi][3]  + gx;
            float oy = t[bi][4]*x + t[bi][5]*y + t[bi][6] *z + t[bi][7]  + yoff + gy;
            float oz = t[bi][8]*x + t[bi][9]*y + t[bi][10]*z + t[bi][11] + gz;
            size_t o = ((size_t)b*V_ + v)*3;
            out[o+0] = ox; out[o+1] = oy; out[o+2] = oz;
        }
    }
}

// ============== launch ==============
extern "C" void kernel_launch(void* const* d_in, const int* in_sizes, int n_in,
                              void* d_out, int out_size)
{
    const float* shape       = (const float*)d_in[0];   // (1,10)
    const float* body_pose   = (const float*)d_in[1];   // (B,21,3)
    const float* hand_pose   = (const float*)d_in[2];   // (B,30,3)
    const float* head_pose   = (const float*)d_in[3];   // (B,3,3)
    const float* expression  = (const float*)d_in[4];   // (B,10)
    const float* pelvis_rot  = (const float*)d_in[5];   // (B,3)
    const float* gtrans      = (const float*)d_in[6];   // (B,3)
    const float* v_template  = (const float*)d_in[7];   // (V,3)
    const float* shapedirs   = (const float*)d_in[8];   // (V,3,10)
    const float* exprdirs    = (const float*)d_in[9];   // (V,3,10)
    const float* posedirs    = (const float*)d_in[10];  // (486, V*3)
    const float* lbs_weights = (const float*)d_in[11];  // (V,J)
    const float* J_regressor = (const float*)d_in[12];  // (J,V)
    const float* hand_mean   = (const float*)d_in[13];  // (2,45)
    float* out = (float*)d_out;

    k_vbase<<<(V3_ + 255)/256, 256>>>(v_template, shapedirs, shape);
    k_ymin<<<1, 1024>>>(v_template);
    k_jreg<<<J_, 128>>>(J_regressor, exprdirs);
    k_pose<<<B_, 64>>>(body_pose, hand_pose, head_pose, pelvis_rot, hand_mean, expression);
    dim3 grid((V_ + TV - 1)/TV, B_/TB);
    k_main<<<grid, 256>>>(posedirs, lbs_weights, exprdirs, expression, gtrans, out);
}

// round 4
// speedup vs baseline: 1.0081x; 1.0081x over previous
#include <cuda_runtime.h>
#include <math.h>

#define V_   10475
#define J_   55
#define B_   512
#define V3_  (V_*3)     // 31425
#define K486 486

#define TV 16   // vertices per block (main kernel)
#define TB 64   // batches per block
#define KT 32   // K-chunk

// -------- device scratch (no allocations allowed) --------
__device__ __align__(16) float g_vbase[V_*3];
__device__ float g_yoff;
__device__ float g_Jbase[J_*3];
__device__ float g_JE[J_*3*10];
__device__ __align__(16) float g_pf_t[K486*B_];     // transposed pose_feature: [k][b]
__device__ __align__(16) float g_A[B_*J_*12];       // per-joint 3x4 skinning matrices

// ============== Kernel 1: vbase = v_template + shapedirs @ shape ==============
__global__ void k_vbase(const float* __restrict__ vt,
                        const float* __restrict__ shapedirs,
                        const float* __restrict__ shape)
{
    int i = blockIdx.x*256 + threadIdx.x;
    if (i < V3_) {
        float acc = vt[i];
        #pragma unroll
        for (int s = 0; s < 10; s++) acc += shape[s] * shapedirs[i*10 + s];
        g_vbase[i] = acc;
    }
}

// ============== Kernel 2: y offset = -min(v_template[:,1]) ==============
__global__ void k_ymin(const float* __restrict__ vt)
{
    __shared__ float red[1024];
    float m = 1e30f;
    for (int v = threadIdx.x; v < V_; v += 1024) m = fminf(m, vt[v*3 + 1]);
    red[threadIdx.x] = m;
    __syncthreads();
    for (int s = 512; s > 0; s >>= 1) {
        if (threadIdx.x < s) red[threadIdx.x] = fminf(red[threadIdx.x], red[threadIdx.x + s]);
        __syncthreads();
    }
    if (threadIdx.x == 0) g_yoff = -red[0];
}

// ============== Kernel 3: Jbase(j,c) and JE(j,c,e) = JR @ [vbase | exprdirs] ==============
__global__ void k_jreg(const float* __restrict__ JR,
                       const float* __restrict__ exprdirs)
{
    int j = blockIdx.x;
    int tid = threadIdx.x;            // 128 threads
    float acc[33];
    #pragma unroll
    for (int i = 0; i < 33; i++) acc[i] = 0.f;

    for (int v = tid; v < V_; v += 128) {
        float jr = JR[j*V_ + v];
        acc[0] += jr * g_vbase[v*3 + 0];
        acc[1] += jr * g_vbase[v*3 + 1];
        acc[2] += jr * g_vbase[v*3 + 2];
        const float* ed = &exprdirs[v*30];
        #pragma unroll
        for (int i = 0; i < 30; i++) acc[3+i] += jr * ed[i];
    }
    // warp reduce then cross-warp
    __shared__ float red[4][33];
    int lane = tid & 31, w = tid >> 5;
    #pragma unroll
    for (int i = 0; i < 33; i++) {
        float v = acc[i];
        for (int off = 16; off > 0; off >>= 1) v += __shfl_down_sync(0xffffffffu, v, off);
        if (lane == 0) red[w][i] = v;
    }
    __syncthreads();
    if (tid < 33) {
        float s = red[0][tid] + red[1][tid] + red[2][tid] + red[3][tid];
        if (tid < 3) g_Jbase[j*3 + tid] = s;
        else         g_JE[j*30 + (tid-3)] = s;
    }
}

// ============== Kernel 4: per-batch rodrigues, pose_feature, joints, chain, A ==============
__global__ void k_pose(const float* __restrict__ body,
                       const float* __restrict__ hand,
                       const float* __restrict__ head,
                       const float* __restrict__ pelvis,
                       const float* __restrict__ hand_mean,
                       const float* __restrict__ expression)
{
    int b = blockIdx.x;
    int tid = threadIdx.x;            // 64 threads
    __shared__ float R_s[J_][9];
    __shared__ float jnt[J_][3];

    if (tid < J_) {
        float r0, r1, r2;
        if (tid == 0) {
            r0 = pelvis[b*3+0]; r1 = pelvis[b*3+1]; r2 = pelvis[b*3+2];
        } else if (tid <= 21) {
            int i = tid - 1;
            r0 = body[(b*21+i)*3+0]; r1 = body[(b*21+i)*3+1]; r2 = body[(b*21+i)*3+2];
        } else if (tid <= 24) {
            int i = tid - 22;
            r0 = head[(b*3+i)*3+0]; r1 = head[(b*3+i)*3+1]; r2 = head[(b*3+i)*3+2];
        } else {
            int h = tid - 25;
            r0 = hand[(b*30+h)*3+0] + hand_mean[h*3+0];
            r1 = hand[(b*30+h)*3+1] + hand_mean[h*3+1];
            r2 = hand[(b*30+h)*3+2] + hand_mean[h*3+2];
        }
        float a2  = r0*r0 + r1*r1 + r2*r2 + 1e-12f;
        float ang = sqrtf(a2);
        float inv = 1.0f / ang;
        float kx = r0*inv, ky = r1*inv, kz = r2*inv;
        float s, c;
        __sincosf(ang, &s, &c);
        // use precise versions: tolerance is generous but keep it clean
        s = sinf(ang); c = cosf(ang);
        float t1 = 1.0f - c;
        float R[9];
        R[0] = c + t1*kx*kx;     R[1] = t1*kx*ky - s*kz;  R[2] = t1*kx*kz + s*ky;
        R[3] = t1*kx*ky + s*kz;  R[4] = c + t1*ky*ky;     R[5] = t1*ky*kz - s*kx;
        R[6] = t1*kx*kz - s*ky;  R[7] = t1*ky*kz + s*kx;  R[8] = c + t1*kz*kz;
        #pragma unroll
        for (int i = 0; i < 9; i++) R_s[tid][i] = R[i];
        if (tid >= 1) {
            #pragma unroll
            for (int i = 0; i < 9; i++) {
                float d = (i == 0 || i == 4 || i == 8) ? 1.0f : 0.0f;
                g_pf_t[((tid-1)*9 + i)*B_ + b] = R[i] - d;
            }
        }
        // joints(b, tid, c) = Jbase + JE . expr
        #pragma unroll
        for (int cc = 0; cc < 3; cc++) {
            float acc = g_Jbase[tid*3 + cc];
            #pragma unroll
            for (int e = 0; e < 10; e++)
                acc += expression[b*10 + e] * g_JE[(tid*3 + cc)*10 + e];
            jnt[tid][cc] = acc;
        }
    }
    __syncthreads();

    if (tid < 3) {
        int r = tid;
        // G_0 row r
        float g0 = R_s[0][r*3+0], g1 = R_s[0][r*3+1], g2 = R_s[0][r*3+2], g3 = jnt[0][r];
        // A_0
        g_A[(b*J_ + 0)*12 + r*4 + 0] = g0;
        g_A[(b*J_ + 0)*12 + r*4 + 1] = g1;
        g_A[(b*J_ + 0)*12 + r*4 + 2] = g2;
        g_A[(b*J_ + 0)*12 + r*4 + 3] = g3 - (g0*jnt[0][0] + g1*jnt[0][1] + g2*jnt[0][2]);
        for (int j = 1; j < J_; j++) {
            float t0 = jnt[j][0] - jnt[j-1][0];
            float t1 = jnt[j][1] - jnt[j-1][1];
            float t2 = jnt[j][2] - jnt[j-1][2];
            float n0 = g0*R_s[j][0] + g1*R_s[j][3] + g2*R_s[j][6];
            float n1 = g0*R_s[j][1] + g1*R_s[j][4] + g2*R_s[j][7];
            float n2 = g0*R_s[j][2] + g1*R_s[j][5] + g2*R_s[j][8];
            float n3 = g0*t0 + g1*t1 + g2*t2 + g3;
            g0 = n0; g1 = n1; g2 = n2; g3 = n3;
            g_A[(b*J_ + j)*12 + r*4 + 0] = g0;
            g_A[(b*J_ + j)*12 + r*4 + 1] = g1;
            g_A[(b*J_ + j)*12 + r*4 + 2] = g2;
            g_A[(b*J_ + j)*12 + r*4 + 3] = g3 - (g0*jnt[j][0] + g1*jnt[j][1] + g2*jnt[j][2]);
        }
    }
}

// ============== Kernel 5: fused pose-blendshape GEMM + expression + LBS + epilogue ==============
__global__ void __launch_bounds__(256) k_main(const float* __restrict__ posedirs,
                                              const float* __restrict__ lbsw,
                                              const float* __restrict__ exprdirs,
                                              const float* __restrict__ expression,
                                              const float* __restrict__ gtrans,
                                              float* __restrict__ out)
{
    __shared__ float pf_s[KT][TB];                  // 8 KB
    __shared__ float pd_s[KT][TV*3];                // 6 KB
    __shared__ float ed_s[TV][30];                  // 1.9 KB
    __shared__ float ex_s[TB][10];                  // 2.5 KB
    __shared__ __align__(16) float A_s[8][TB][12];  // 24 KB
    __shared__ float W_s[TV][56];                   // 3.5 KB
    __shared__ float vb_s[TV][3];

    const int v0 = blockIdx.x * TV;
    const int b0 = blockIdx.y * TB;
    const int tid = threadIdx.x;
    const int vx = tid & 15;        // vertex within tile
    const int by = tid >> 4;        // batch sub-index (thread handles by, by+16, by+32, by+48)

    // ---- one-time tile loads ----
    for (int i = tid; i < TV*56; i += 256) {
        int vv = i / 56, j = i % 56;
        float w = 0.f;
        if (j < J_ && v0 + vv < V_) w = lbsw[(v0+vv)*J_ + j];
        W_s[vv][j] = w;
    }
    for (int i = tid; i < TV*30; i += 256) {
        int vv = i / 30, e = i % 30;
        ed_s[vv][e] = (v0 + vv < V_) ? exprdirs[(v0+vv)*30 + e] : 0.f;
    }
    for (int i = tid; i < TB*10; i += 256)
        ex_s[i/10][i%10] = expression[(b0 + i/10)*10 + (i%10)];
    for (int i = tid; i < TV*3; i += 256)
        vb_s[i/3][i%3] = (v0 + i/3 < V_) ? g_vbase[(v0 + i/3)*3 + (i%3)] : 0.f;

    // ---- phase A: delta(b, v, c) = PF(b,:) @ posedirs(:, 3v+c) ----
    float d[4][3];
    #pragma unroll
    for (int bi = 0; bi < 4; bi++) { d[bi][0] = d[bi][1] = d[bi][2] = 0.f; }

    for (int k0 = 0; k0 < K486; k0 += KT) {
        __syncthreads();
        for (int i = tid; i < KT*TB; i += 256) {
            int k = i / TB, bb = i % TB;
            pf_s[k][bb] = (k0 + k < K486) ? g_pf_t[(k0+k)*B_ + b0 + bb] : 0.f;
        }
        for (int i = tid; i < KT*TV*3; i += 256) {
            int k = i / (TV*3), c = i % (TV*3);
            int col = v0*3 + c;
            pd_s[k][c] = (k0 + k < K486 && col < V3_) ? posedirs[(size_t)(k0+k)*V3_ + col] : 0.f;
        }
        __syncthreads();
        #pragma unroll 8
        for (int k = 0; k < KT; k++) {
            float p0 = pd_s[k][vx*3+0];
            float p1 = pd_s[k][vx*3+1];
            float p2 = pd_s[k][vx*3+2];
            #pragma unroll
            for (int bi = 0; bi < 4; bi++) {
                float f = pf_s[k][by + bi*16];
                d[bi][0] += f*p0; d[bi][1] += f*p1; d[bi][2] += f*p2;
            }
        }
    }

    // ---- phase B: v_posed = vbase + delta + exprdirs . expression ----
    float px[4], py[4], pz[4];
    #pragma unroll
    for (int bi = 0; bi < 4; bi++) {
        int bb = by + bi*16;
        float x = vb_s[vx][0] + d[bi][0];
        float y = vb_s[vx][1] + d[bi][1];
        float z = vb_s[vx][2] + d[bi][2];
        #pragma unroll
        for (int e = 0; e < 10; e++) {
            float ex = ex_s[bb][e];
            x += ex * ed_s[vx][e];
            y += ex * ed_s[vx][10+e];
            z += ex * ed_s[vx][20+e];
        }
        px[bi] = x; py[bi] = y; pz[bi] = z;
    }

    // ---- phase C: LBS — T(b,v) = sum_j w(v,j) A(b,j) ----
    float t[4][12];
    #pragma unroll
    for (int bi = 0; bi < 4; bi++)
        #pragma unroll
        for (int q = 0; q < 12; q++) t[bi][q] = 0.f;

    for (int j0 = 0; j0 < J_; j0 += 8) {
        __syncthreads();
        for (int i = tid; i < TB*8*3; i += 256) {
            int bb  = i / 24;
            int rem = i % 24;
            int jj  = rem / 3;
            int q   = rem % 3;
            float4 val = make_float4(0.f, 0.f, 0.f, 0.f);
            if (j0 + jj < J_)
                val = *reinterpret_cast<const float4*>(&g_A[((size_t)(b0+bb)*J_ + (j0+jj))*12 + q*4]);
            *reinterpret_cast<float4*>(&A_s[jj][bb][q*4]) = val;
        }
        __syncthreads();
        #pragma unroll
        for (int jj = 0; jj < 8; jj++) {
            float w = W_s[vx][j0 + jj];
            #pragma unroll
            for (int bi = 0; bi < 4; bi++) {
                const float4* ap = reinterpret_cast<const float4*>(&A_s[jj][by + bi*16][0]);
                float4 a0 = ap[0], a1 = ap[1], a2 = ap[2];
                t[bi][0]  += w*a0.x; t[bi][1]  += w*a0.y; t[bi][2]  += w*a0.z; t[bi][3]  += w*a0.w;
                t[bi][4]  += w*a1.x; t[bi][5]  += w*a1.y; t[bi][6]  += w*a1.z; t[bi][7]  += w*a1.w;
                t[bi][8]  += w*a2.x; t[bi][9]  += w*a2.y; t[bi][10] += w*a2.z; t[bi][11] += w*a2.w;
            }
        }
    }

    // ---- epilogue ----
    int v = v0 + vx;
    if (v < V_) {
        float yoff = g_yoff;
        #pragma unroll
        for (int bi = 0; bi < 4; bi++) {
            int b = b0 + by + bi*16;
            float gx = gtrans[b*3+0], gy = gtrans[b*3+1], gz = gtrans[b*3+2];
            float x = px[bi], y = py[bi], z = pz[bi];
            float ox = t[bi][0]*x + t[bi][1]*y + t[bi][2] *z + t[bi][3]  + gx;
            float oy = t[bi][4]*x + t[bi][5]*y + t[bi][6] *z + t[bi][7]  + yoff + gy;
            float oz = t[bi][8]*x + t[bi][9]*y + t[bi][10]*z + t[bi][11] + gz;
            size_t o = ((size_t)b*V_ + v)*3;
            out[o+0] = ox; out[o+1] = oy; out[o+2] = oz;
        }
    }
}

// ============== launch ==============
extern "C" void kernel_launch(void* const* d_in, const int* in_sizes, int n_in,
                              void* d_out, int out_size)
{
    const float* shape       = (const float*)d_in[0];   // (1,10)
    const float* body_pose   = (const float*)d_in[1];   // (B,21,3)
    const float* hand_pose   = (const float*)d_in[2];   // (B,30,3)
    const float* head_pose   = (const float*)d_in[3];   // (B,3,3)
    const float* expression  = (const float*)d_in[4];   // (B,10)
    const float* pelvis_rot  = (const float*)d_in[5];   // (B,3)
    const float* gtrans      = (const float*)d_in[6];   // (B,3)
    const float* v_template  = (const float*)d_in[7];   // (V,3)
    const float* shapedirs   = (const float*)d_in[8];   // (V,3,10)
    const float* exprdirs    = (const float*)d_in[9];   // (V,3,10)
    const float* posedirs    = (const float*)d_in[10];  // (486, V*3)
    const float* lbs_weights = (const float*)d_in[11];  // (V,J)
    const float* J_regressor = (const float*)d_in[12];  // (J,V)
    const float* hand_mean   = (const float*)d_in[13];  // (2,45)
    float* out = (float*)d_out;

    k_vbase<<<(V3_ + 255)/256, 256>>>(v_template, shapedirs, shape);
    k_ymin<<<1, 1024>>>(v_template);
    k_jreg<<<J_, 128>>>(J_regressor, exprdirs);
    k_pose<<<B_, 64>>>(body_pose, hand_pose, head_pose, pelvis_rot, hand_mean, expression);
    dim3 grid((V_ + TV - 1)/TV, B_/TB);
    k_main<<<grid, 256>>>(posedirs, lbs_weights, exprdirs, expression, gtrans, out);
}

// round 5
// speedup vs baseline: 1.0094x; 1.0013x over previous
#include <cuda_runtime.h>
#include <math.h>

#define V_   10475
#define J_   55
#define B_   512
#define V3_  (V_*3)     // 31425
#define K486 486

#define TV 16   // vertices per block (main kernel)
#define TB 64   // batches per block
#define KT 32   // K-chunk

// -------- device scratch (no allocations allowed) --------
__device__ __align__(16) float g_vbase[V_*3];
__device__ float g_yoff;
__device__ float g_Jbase[J_*3];
__device__ float g_JE[J_*3*10];
__device__ __align__(16) float g_pf_t[K486*B_];     // transposed pose_feature: [k][b]
__device__ __align__(16) float g_A[B_*J_*12];       // per-joint 3x4 skinning matrices

// ============== Kernel 1: vbase = v_template + shapedirs @ shape ==============
__global__ void k_vbase(const float* __restrict__ vt,
                        const float* __restrict__ shapedirs,
                        const float* __restrict__ shape)
{
    int i = blockIdx.x*256 + threadIdx.x;
    if (i < V3_) {
        float acc = vt[i];
        #pragma unroll
        for (int s = 0; s < 10; s++) acc += shape[s] * shapedirs[i*10 + s];
        g_vbase[i] = acc;
    }
}

// ============== Kernel 2: y offset = -min(v_template[:,1]) ==============
__global__ void k_ymin(const float* __restrict__ vt)
{
    __shared__ float red[1024];
    float m = 1e30f;
    for (int v = threadIdx.x; v < V_; v += 1024) m = fminf(m, vt[v*3 + 1]);
    red[threadIdx.x] = m;
    __syncthreads();
    for (int s = 512; s > 0; s >>= 1) {
        if (threadIdx.x < s) red[threadIdx.x] = fminf(red[threadIdx.x], red[threadIdx.x + s]);
        __syncthreads();
    }
    if (threadIdx.x == 0) g_yoff = -red[0];
}

// ============== Kernel 3: Jbase(j,c) and JE(j,c,e) = JR @ [vbase | exprdirs] ==============
__global__ void k_jreg(const float* __restrict__ JR,
                       const float* __restrict__ exprdirs)
{
    int j = blockIdx.x;
    int tid = threadIdx.x;            // 128 threads
    float acc[33];
    #pragma unroll
    for (int i = 0; i < 33; i++) acc[i] = 0.f;

    for (int v = tid; v < V_; v += 128) {
        float jr = JR[j*V_ + v];
        acc[0] += jr * g_vbase[v*3 + 0];
        acc[1] += jr * g_vbase[v*3 + 1];
        acc[2] += jr * g_vbase[v*3 + 2];
        const float* ed = &exprdirs[v*30];
        #pragma unroll
        for (int i = 0; i < 30; i++) acc[3+i] += jr * ed[i];
    }
    // warp reduce then cross-warp
    __shared__ float red[4][33];
    int lane = tid & 31, w = tid >> 5;
    #pragma unroll
    for (int i = 0; i < 33; i++) {
        float v = acc[i];
        for (int off = 16; off > 0; off >>= 1) v += __shfl_down_sync(0xffffffffu, v, off);
        if (lane == 0) red[w][i] = v;
    }
    __syncthreads();
    if (tid < 33) {
        float s = red[0][tid] + red[1][tid] + red[2][tid] + red[3][tid];
        if (tid < 3) g_Jbase[j*3 + tid] = s;
        else         g_JE[j*30 + (tid-3)] = s;
    }
}

// ============== Kernel 4: per-batch rodrigues, pose_feature, joints, chain, A ==============
__global__ void k_pose(const float* __restrict__ body,
                       const float* __restrict__ hand,
                       const float* __restrict__ head,
                       const float* __restrict__ pelvis,
                       const float* __restrict__ hand_mean,
                       const float* __restrict__ expression)
{
    int b = blockIdx.x;
    int tid = threadIdx.x;            // 64 threads
    __shared__ float R_s[J_][9];
    __shared__ float jnt[J_][3];

    if (tid < J_) {
        float r0, r1, r2;
        if (tid == 0) {
            r0 = pelvis[b*3+0]; r1 = pelvis[b*3+1]; r2 = pelvis[b*3+2];
        } else if (tid <= 21) {
            int i = tid - 1;
            r0 = body[(b*21+i)*3+0]; r1 = body[(b*21+i)*3+1]; r2 = body[(b*21+i)*3+2];
        } else if (tid <= 24) {
            int i = tid - 22;
            r0 = head[(b*3+i)*3+0]; r1 = head[(b*3+i)*3+1]; r2 = head[(b*3+i)*3+2];
        } else {
            int h = tid - 25;
            r0 = hand[(b*30+h)*3+0] + hand_mean[h*3+0];
            r1 = hand[(b*30+h)*3+1] + hand_mean[h*3+1];
            r2 = hand[(b*30+h)*3+2] + hand_mean[h*3+2];
        }
        float a2  = r0*r0 + r1*r1 + r2*r2 + 1e-12f;
        float ang = sqrtf(a2);
        float inv = 1.0f / ang;
        float kx = r0*inv, ky = r1*inv, kz = r2*inv;
        float s, c;
        __sincosf(ang, &s, &c);
        // use precise versions: tolerance is generous but keep it clean
        s = sinf(ang); c = cosf(ang);
        float t1 = 1.0f - c;
        float R[9];
        R[0] = c + t1*kx*kx;     R[1] = t1*kx*ky - s*kz;  R[2] = t1*kx*kz + s*ky;
        R[3] = t1*kx*ky + s*kz;  R[4] = c + t1*ky*ky;     R[5] = t1*ky*kz - s*kx;
        R[6] = t1*kx*kz - s*ky;  R[7] = t1*ky*kz + s*kx;  R[8] = c + t1*kz*kz;
        #pragma unroll
        for (int i = 0; i < 9; i++) R_s[tid][i] = R[i];
        if (tid >= 1) {
            #pragma unroll
            for (int i = 0; i < 9; i++) {
                float d = (i == 0 || i == 4 || i == 8) ? 1.0f : 0.0f;
                g_pf_t[((tid-1)*9 + i)*B_ + b] = R[i] - d;
            }
        }
        // joints(b, tid, c) = Jbase + JE . expr
        #pragma unroll
        for (int cc = 0; cc < 3; cc++) {
            float acc = g_Jbase[tid*3 + cc];
            #pragma unroll
            for (int e = 0; e < 10; e++)
                acc += expression[b*10 + e] * g_JE[(tid*3 + cc)*10 + e];
            jnt[tid][cc] = acc;
        }
    }
    __syncthreads();

    if (tid < 3) {
        int r = tid;
        // G_0 row r
        float g0 = R_s[0][r*3+0], g1 = R_s[0][r*3+1], g2 = R_s[0][r*3+2], g3 = jnt[0][r];
        // A_0
        g_A[(b*J_ + 0)*12 + r*4 + 0] = g0;
        g_A[(b*J_ + 0)*12 + r*4 + 1] = g1;
        g_A[(b*J_ + 0)*12 + r*4 + 2] = g2;
        g_A[(b*J_ + 0)*12 + r*4 + 3] = g3 - (g0*jnt[0][0] + g1*jnt[0][1] + g2*jnt[0][2]);
        for (int j = 1; j < J_; j++) {
            float t0 = jnt[j][0] - jnt[j-1][0];
            float t1 = jnt[j][1] - jnt[j-1][1];
            float t2 = jnt[j][2] - jnt[j-1][2];
            float n0 = g0*R_s[j][0] + g1*R_s[j][3] + g2*R_s[j][6];
            float n1 = g0*R_s[j][1] + g1*R_s[j][4] + g2*R_s[j][7];
            float n2 = g0*R_s[j][2] + g1*R_s[j][5] + g2*R_s[j][8];
            float n3 = g0*t0 + g1*t1 + g2*t2 + g3;
            g0 = n0; g1 = n1; g2 = n2; g3 = n3;
            g_A[(b*J_ + j)*12 + r*4 + 0] = g0;
            g_A[(b*J_ + j)*12 + r*4 + 1] = g1;
            g_A[(b*J_ + j)*12 + r*4 + 2] = g2;
            g_A[(b*J_ + j)*12 + r*4 + 3] = g3 - (g0*jnt[j][0] + g1*jnt[j][1] + g2*jnt[j][2]);
        }
    }
}

// ============== Kernel 5: fused pose-blendshape GEMM + expression + LBS + epilogue ==============
__global__ void __launch_bounds__(256) k_main(const float* __restrict__ posedirs,
                                              const float* __restrict__ lbsw,
                                              const float* __restrict__ exprdirs,
                                              const float* __restrict__ expression,
                                              const float* __restrict__ gtrans,
                                              float* __restrict__ out)
{
    __shared__ float pf_s[KT][TB];                  // 8 KB
    __shared__ float pd_s[KT][TV*3];                // 6 KB
    __shared__ float ed_s[TV][30];                  // 1.9 KB
    __shared__ float ex_s[TB][10];                  // 2.5 KB
    __shared__ __align__(16) float A_s[8][TB][12];  // 24 KB
    __shared__ float W_s[TV][56];                   // 3.5 KB
    __shared__ float vb_s[TV][3];

    const int v0 = blockIdx.x * TV;
    const int b0 = blockIdx.y * TB;
    const int tid = threadIdx.x;
    const int vx = tid & 15;        // vertex within tile
    const int by = tid >> 4;        // batch sub-index (thread handles by, by+16, by+32, by+48)

    // ---- one-time tile loads ----
    for (int i = tid; i < TV*56; i += 256) {
        int vv = i / 56, j = i % 56;
        float w = 0.f;
        if (j < J_ && v0 + vv < V_) w = lbsw[(v0+vv)*J_ + j];
        W_s[vv][j] = w;
    }
    for (int i = tid; i < TV*30; i += 256) {
        int vv = i / 30, e = i % 30;
        ed_s[vv][e] = (v0 + vv < V_) ? exprdirs[(v0+vv)*30 + e] : 0.f;
    }
    for (int i = tid; i < TB*10; i += 256)
        ex_s[i/10][i%10] = expression[(b0 + i/10)*10 + (i%10)];
    for (int i = tid; i < TV*3; i += 256)
        vb_s[i/3][i%3] = (v0 + i/3 < V_) ? g_vbase[(v0 + i/3)*3 + (i%3)] : 0.f;

    // ---- phase A: delta(b, v, c) = PF(b,:) @ posedirs(:, 3v+c) ----
    float d[4][3];
    #pragma unroll
    for (int bi = 0; bi < 4; bi++) { d[bi][0] = d[bi][1] = d[bi][2] = 0.f; }

    for (int k0 = 0; k0 < K486; k0 += KT) {
        __syncthreads();
        for (int i = tid; i < KT*TB; i += 256) {
            int k = i / TB, bb = i % TB;
            pf_s[k][bb] = (k0 + k < K486) ? g_pf_t[(k0+k)*B_ + b0 + bb] : 0.f;
        }
        for (int i = tid; i < KT*TV*3; i += 256) {
            int k = i / (TV*3), c = i % (TV*3);
            int col = v0*3 + c;
            pd_s[k][c] = (k0 + k < K486 && col < V3_) ? posedirs[(size_t)(k0+k)*V3_ + col] : 0.f;
        }
        __syncthreads();
        #pragma unroll 8
        for (int k = 0; k < KT; k++) {
            float p0 = pd_s[k][vx*3+0];
            float p1 = pd_s[k][vx*3+1];
            float p2 = pd_s[k][vx*3+2];
            #pragma unroll
            for (int bi = 0; bi < 4; bi++) {
                float f = pf_s[k][by + bi*16];
                d[bi][0] += f*p0; d[bi][1] += f*p1; d[bi][2] += f*p2;
            }
        }
    }

    // ---- phase B: v_posed = vbase + delta + exprdirs . expression ----
    float px[4], py[4], pz[4];
    #pragma unroll
    for (int bi = 0; bi < 4; bi++) {
        int bb = by + bi*16;
        float x = vb_s[vx][0] + d[bi][0];
        float y = vb_s[vx][1] + d[bi][1];
        float z = vb_s[vx][2] + d[bi][2];
        #pragma unroll
        for (int e = 0; e < 10; e++) {
            float ex = ex_s[bb][e];
            x += ex * ed_s[vx][e];
            y += ex * ed_s[vx][10+e];
            z += ex * ed_s[vx][20+e];
        }
        px[bi] = x; py[bi] = y; pz[bi] = z;
    }

    // ---- phase C: LBS — T(b,v) = sum_j w(v,j) A(b,j) ----
    float t[4][12];
    #pragma unroll
    for (int bi = 0; bi < 4; bi++)
        #pragma unroll
        for (int q = 0; q < 12; q++) t[bi][q] = 0.f;

    for (int j0 = 0; j0 < J_; j0 += 8) {
        __syncthreads();
        for (int i = tid; i < TB*8*3; i += 256) {
            int bb  = i / 24;
            int rem = i % 24;
            int jj  = rem / 3;
            int q   = rem % 3;
            float4 val = make_float4(0.f, 0.f, 0.f, 0.f);
            if (j0 + jj < J_)
                val = *reinterpret_cast<const float4*>(&g_A[((size_t)(b0+bb)*J_ + (j0+jj))*12 + q*4]);
            *reinterpret_cast<float4*>(&A_s[jj][bb][q*4]) = val;
        }
        __syncthreads();
        #pragma unroll
        for (int jj = 0; jj < 8; jj++) {
            float w = W_s[vx][j0 + jj];
            #pragma unroll
            for (int bi = 0; bi < 4; bi++) {
                const float4* ap = reinterpret_cast<const float4*>(&A_s[jj][by + bi*16][0]);
                float4 a0 = ap[0], a1 = ap[1], a2 = ap[2];
                t[bi][0]  += w*a0.x; t[bi][1]  += w*a0.y; t[bi][2]  += w*a0.z; t[bi][3]  += w*a0.w;
                t[bi][4]  += w*a1.x; t[bi][5]  += w*a1.y; t[bi][6]  += w*a1.z; t[bi][7]  += w*a1.w;
                t[bi][8]  += w*a2.x; t[bi][9]  += w*a2.y; t[bi][10] += w*a2.z; t[bi][11] += w*a2.w;
            }
        }
    }

    // ---- epilogue ----
    int v = v0 + vx;
    if (v < V_) {
        float yoff = g_yoff;
        #pragma unroll
        for (int bi = 0; bi < 4; bi++) {
            int b = b0 + by + bi*16;
            float gx = gtrans[b*3+0], gy = gtrans[b*3+1], gz = gtrans[b*3+2];
            float x = px[bi], y = py[bi], z = pz[bi];
            float ox = t[bi][0]*x + t[bi][1]*y + t[bi][2] *z + t[bi][3]  + gx;
            float oy = t[bi][4]*x + t[bi][5]*y + t[bi][6] *z + t[bi][7]  + yoff + gy;
            float oz = t[bi][8]*x + t[bi][9]*y + t[bi][10]*z + t[bi][11] + gz;
            size_t o = ((size_t)b*V_ + v)*3;
            out[o+0] = ox; out[o+1] = oy; out[o+2] = oz;
        }
    }
}

// ============== launch ==============
extern "C" void kernel_launch(void* const* d_in, const int* in_sizes, int n_in,
                              void* d_out, int out_size)
{
    const float* shape       = (const float*)d_in[0];   // (1,10)
    const float* body_pose   = (const float*)d_in[1];   // (B,21,3)
    const float* hand_pose   = (const float*)d_in[2];   // (B,30,3)
    const float* head_pose   = (const float*)d_in[3];   // (B,3,3)
    const float* expression  = (const float*)d_in[4];   // (B,10)
    const float* pelvis_rot  = (const float*)d_in[5];   // (B,3)
    const float* gtrans      = (const float*)d_in[6];   // (B,3)
    const float* v_template  = (const float*)d_in[7];   // (V,3)
    const float* shapedirs   = (const float*)d_in[8];   // (V,3,10)
    const float* exprdirs    = (const float*)d_in[9];   // (V,3,10)
    const float* posedirs    = (const float*)d_in[10];  // (486, V*3)
    const float* lbs_weights = (const float*)d_in[11];  // (V,J)
    const float* J_regressor = (const float*)d_in[12];  // (J,V)
    const float* hand_mean   = (const float*)d_in[13];  // (2,45)
    float* out = (float*)d_out;

    k_vbase<<<(V3_ + 255)/256, 256>>>(v_template, shapedirs, shape);
    k_ymin<<<1, 1024>>>(v_template);
    k_jreg<<<J_, 128>>>(J_regressor, exprdirs);
    k_pose<<<B_, 64>>>(body_pose, hand_pose, head_pose, pelvis_rot, hand_mean, expression);
    dim3 grid((V_ + TV - 1)/TV, B_/TB);
    k_main<<<grid, 256>>>(posedirs, lbs_weights, exprdirs, expression, gtrans, out);
}